// round 16
// baseline (speedup 1.0000x reference)
#include <cuda_runtime.h>
#include <cuda_bf16.h>
#include <cuda_fp16.h>
#include <math.h>

#define NN    50000
#define EE    800000
#define INCH  128
#define HID   64
#define HEADS 4
#define ACT   5

// ---------------- scratch ----------------
__device__ float g_out1[NN * 256];
__device__ float g_asrc1[NN * 4];
__device__ float g_adst1[NN * 4];
__device__ float g_g2[NN * 64];
__device__ float g_asrc2[NN];
__device__ float g_adst2[NN];
__device__ float g_w1a[128 * 8];
__device__ __half g_xh[NN * 128];        // fp16 copy of x for the gather
__device__ int   g_cnt[NN];
__device__ int   g_off[NN + 1];
__device__ int   g_pos[NN];
__device__ int   g_csr[EE + NN];
__device__ float g_p[(EE + NN) * 4];

__device__ __forceinline__ float lrelu(float x) { return x > 0.0f ? x : 0.2f * x; }

__device__ __forceinline__ unsigned f2tf32(float f) {
    unsigned u;
    asm("cvt.rna.tf32.f32 %0, %1;" : "=r"(u) : "f"(f));
    return u;
}

__device__ __forceinline__ void mma_tf32(float& d0, float& d1, float& d2, float& d3,
                                         unsigned a0, unsigned a1, unsigned a2, unsigned a3,
                                         unsigned b0, unsigned b1) {
    asm volatile("mma.sync.aligned.m16n8k8.row.col.f32.tf32.tf32.f32 "
                 "{%0,%1,%2,%3},{%4,%5,%6,%7},{%8,%9},{%0,%1,%2,%3};"
                 : "+f"(d0), "+f"(d1), "+f"(d2), "+f"(d3)
                 : "r"(a0), "r"(a1), "r"(a2), "r"(a3), "r"(b0), "r"(b1));
}

// fp16x4 -> float4
__device__ __forceinline__ float4 xh_load(const __half* p) {
    uint2 h = *(const uint2*)p;
    float2 lo = __half22float2(*(__half2*)&h.x);
    float2 hi = __half22float2(*(__half2*)&h.y);
    return make_float4(lo.x, lo.y, hi.x, hi.y);
}

#define CVT_B ((NN * 128 / 16 + 255) / 256)   // 1563 blocks, 16 floats/thread

// ============ K0: histogram (2 edges/thread) + w1a precompute + x->fp16 convert ============
__global__ void hist_wpre(const int* __restrict__ ei, int E, int histB,
                          const float* __restrict__ W1,
                          const float* __restrict__ a1s,
                          const float* __restrict__ a1d,
                          const float* __restrict__ x) {
    if ((int)blockIdx.x < histB) {
        int e0 = blockIdx.x * 512 + threadIdx.x;
        int e1 = e0 + 256;
        int d0 = (e0 < E) ? ei[E + e0] : -1;
        int d1 = (e1 < E) ? ei[E + e1] : -1;
        if (d0 >= 0) atomicAdd(&g_cnt[d0], 1);
        if (d1 >= 0) atomicAdd(&g_cnt[d1], 1);
    } else if ((int)blockIdx.x < histB + 4) {
        int t = (blockIdx.x - histB) * 256 + threadIdx.x;
        if (t < 1024) {
            int k = t >> 3, j = t & 7, h = j & 3;
            const float* av = (j < 4 ? a1s : a1d) + h * 64;
            const float* wr = W1 + (size_t)k * 256 + h * 64;
            float s = 0.f;
#pragma unroll 8
            for (int c = 0; c < 64; c++) s += wr[c] * av[c];
            g_w1a[k * 8 + j] = s;
        }
    } else {
        size_t base = ((size_t)(blockIdx.x - histB - 4) * 256 + threadIdx.x) * 16;
        if (base < (size_t)NN * 128) {
#pragma unroll
            for (int j = 0; j < 4; j++) {
                float4 v = *(const float4*)&x[base + j * 4];
                __half2 h0 = __floats2half2_rn(v.x, v.y);
                __half2 h1 = __floats2half2_rn(v.z, v.w);
                uint2 pk;
                pk.x = *(unsigned*)&h0;
                pk.y = *(unsigned*)&h1;
                *(uint2*)&g_xh[base + j * 4] = pk;
            }
        }
    }
}

// ============ K1: scan (block 0) + alpha1 (blocks 1..) ============
__global__ void __launch_bounds__(1024) scan_alpha(const float* __restrict__ x) {
    __shared__ float w1s[128 * 8];
    if (blockIdx.x == 0) {
        __shared__ int ws[32];
        const int T = 1024;
        const int CH = (NN + T - 1) / T;
        int tid = threadIdx.x;
        int base = tid * CH;
        int cnts[49];
        int local = 0;
        for (int j = 0; j < CH; j++) {
            int idx = base + j;
            int c = 0;
            if (idx < NN) { c = g_cnt[idx] + 1; g_cnt[idx] = 0; }
            cnts[j] = c;
            local += c;
        }
        int lane = tid & 31, wid = tid >> 5;
        int v = local;
#pragma unroll
        for (int o = 1; o < 32; o <<= 1) { int y = __shfl_up_sync(~0u, v, o); if (lane >= o) v += y; }
        if (lane == 31) ws[wid] = v;
        __syncthreads();
        if (wid == 0) {
            int w = ws[lane];
#pragma unroll
            for (int o = 1; o < 32; o <<= 1) { int y = __shfl_up_sync(~0u, w, o); if (lane >= o) w += y; }
            ws[lane] = w;
        }
        __syncthreads();
        int run = v - local + (wid > 0 ? ws[wid - 1] : 0);
        for (int j = 0; j < CH; j++) {
            int idx = base + j;
            if (idx < NN) {
                g_off[idx] = run;
                g_pos[idx] = run;
                run += cnts[j];
            }
        }
        if (tid == T - 1) g_off[NN] = run;
    } else {
        int tid = threadIdx.x;
        if (tid < 1024) w1s[tid] = g_w1a[tid];
        __syncthreads();
        int wid = tid >> 5, lane = tid & 31;
        int node = (blockIdx.x - 1) * 32 + wid;
        if (node >= NN) return;
        float4 xv = *(const float4*)&x[(size_t)node * 128 + lane * 4];
        float s[8];
#pragma unroll
        for (int j = 0; j < 8; j++) s[j] = 0.f;
#pragma unroll
        for (int k = 0; k < 4; k++) {
            float xk = (&xv.x)[k];
            const float* wr = &w1s[(lane * 4 + k) * 8];
            float4 wa = *(const float4*)&wr[0];
            float4 wb = *(const float4*)&wr[4];
            s[0] += xk * wa.x; s[1] += xk * wa.y; s[2] += xk * wa.z; s[3] += xk * wa.w;
            s[4] += xk * wb.x; s[5] += xk * wb.y; s[6] += xk * wb.z; s[7] += xk * wb.w;
        }
#pragma unroll
        for (int j = 0; j < 8; j++) {
#pragma unroll
            for (int o = 16; o > 0; o >>= 1) s[j] += __shfl_xor_sync(~0u, s[j], o);
        }
        if (lane == 0) {
            *(float4*)&g_asrc1[node * 4] = make_float4(s[0], s[1], s[2], s[3]);
            *(float4*)&g_adst1[node * 4] = make_float4(s[4], s[5], s[6], s[7]);
        }
    }
}

// ============ K2: scatter + softmax weights (2 edges/thread) ============
__global__ void scatter_p(const int* __restrict__ ei, int E) {
    int base = (blockIdx.x * blockDim.x + threadIdx.x) * 2;
#pragma unroll
    for (int j = 0; j < 2; j++) {
        int t = base + j;
        int src, dst;
        if (t < E) { src = ei[t]; dst = ei[E + t]; }
        else if (t < E + NN) { src = dst = t - E; }
        else continue;
        int pos = atomicAdd(&g_pos[dst], 1);
        g_csr[pos] = src;
        float4 es = *(const float4*)&g_asrc1[src * 4];
        float4 ed = *(const float4*)&g_adst1[dst * 4];
        float4 p;
        p.x = __expf(lrelu(es.x + ed.x));
        p.y = __expf(lrelu(es.y + ed.y));
        p.z = __expf(lrelu(es.z + ed.z));
        p.w = __expf(lrelu(es.w + ed.w));
        *(float4*)&g_p[(size_t)pos * 4] = p;
    }
}

// ============ K3: fused gather (fp16 x, dynamic queue) + tf32 GEMM1 + epilogue ============
#define L1_SMEM ((128 * 132 + 32 * 260 + 128 + 32) * 4)
__global__ void __launch_bounds__(512, 2) layer1_fused(const float* __restrict__ x,
                                                       const float* __restrict__ W1,
                                                       const float* __restrict__ b1) {
    extern __shared__ float sm[];
    float* As = sm;                       // 128 rows (head*32+node) x 132
    float* Bs = sm + 128 * 132;           // 32 k x 260
    float* dens = Bs + 32 * 260;          // 128
    int*   q = (int*)(dens + 128);
    int tid = threadIdx.x, lane = tid & 31, wid = tid >> 5;
    int node0 = blockIdx.x * 32;

    if (tid == 0) q[0] = 0;
    __syncthreads();

    for (;;) {
        int nl;
        if (lane == 0) nl = atomicAdd(q, 1);
        nl = __shfl_sync(~0u, nl, 0);
        if (nl >= 32) break;
        int node = node0 + nl;
        float4 a0 = make_float4(0,0,0,0), a1 = a0, a2 = a0, a3 = a0;
        float4 dn = a0;
        if (node < NN) {
            int s0 = g_off[node], s1 = g_off[node + 1];
            int i = s0;
            for (; i + 3 < s1; i += 4) {
                int e0 = g_csr[i],     e1 = g_csr[i + 1];
                int e2 = g_csr[i + 2], e3 = g_csr[i + 3];
                float4 p0 = *(const float4*)&g_p[(size_t)(i)     * 4];
                float4 p1 = *(const float4*)&g_p[(size_t)(i + 1) * 4];
                float4 p2 = *(const float4*)&g_p[(size_t)(i + 2) * 4];
                float4 p3 = *(const float4*)&g_p[(size_t)(i + 3) * 4];
                float4 x0 = xh_load(&g_xh[(size_t)e0 * 128 + lane * 4]);
                float4 x1 = xh_load(&g_xh[(size_t)e1 * 128 + lane * 4]);
                float4 x2 = xh_load(&g_xh[(size_t)e2 * 128 + lane * 4]);
                float4 x3 = xh_load(&g_xh[(size_t)e3 * 128 + lane * 4]);
                a0.x += p0.x*x0.x + p1.x*x1.x + p2.x*x2.x + p3.x*x3.x;
                a0.y += p0.x*x0.y + p1.x*x1.y + p2.x*x2.y + p3.x*x3.y;
                a0.z += p0.x*x0.z + p1.x*x1.z + p2.x*x2.z + p3.x*x3.z;
                a0.w += p0.x*x0.w + p1.x*x1.w + p2.x*x2.w + p3.x*x3.w;
                a1.x += p0.y*x0.x + p1.y*x1.x + p2.y*x2.x + p3.y*x3.x;
                a1.y += p0.y*x0.y + p1.y*x1.y + p2.y*x2.y + p3.y*x3.y;
                a1.z += p0.y*x0.z + p1.y*x1.z + p2.y*x2.z + p3.y*x3.z;
                a1.w += p0.y*x0.w + p1.y*x1.w + p2.y*x2.w + p3.y*x3.w;
                a2.x += p0.z*x0.x + p1.z*x1.x + p2.z*x2.x + p3.z*x3.x;
                a2.y += p0.z*x0.y + p1.z*x1.y + p2.z*x2.y + p3.z*x3.y;
                a2.z += p0.z*x0.z + p1.z*x1.z + p2.z*x2.z + p3.z*x3.z;
                a2.w += p0.z*x0.w + p1.z*x1.w + p2.z*x2.w + p3.z*x3.w;
                a3.x += p0.w*x0.x + p1.w*x1.x + p2.w*x2.x + p3.w*x3.x;
                a3.y += p0.w*x0.y + p1.w*x1.y + p2.w*x2.y + p3.w*x3.y;
                a3.z += p0.w*x0.z + p1.w*x1.z + p2.w*x2.z + p3.w*x3.z;
                a3.w += p0.w*x0.w + p1.w*x1.w + p2.w*x2.w + p3.w*x3.w;
                dn.x += p0.x + p1.x + p2.x + p3.x;
                dn.y += p0.y + p1.y + p2.y + p3.y;
                dn.z += p0.z + p1.z + p2.z + p3.z;
                dn.w += p0.w + p1.w + p2.w + p3.w;
            }
            for (; i < s1; i++) {
                int sa = g_csr[i];
                float4 pa = *(const float4*)&g_p[(size_t)i * 4];
                float4 xa = xh_load(&g_xh[(size_t)sa * 128 + lane * 4]);
                a0.x += pa.x * xa.x; a0.y += pa.x * xa.y; a0.z += pa.x * xa.z; a0.w += pa.x * xa.w;
                a1.x += pa.y * xa.x; a1.y += pa.y * xa.y; a1.z += pa.y * xa.z; a1.w += pa.y * xa.w;
                a2.x += pa.z * xa.x; a2.y += pa.z * xa.y; a2.z += pa.z * xa.z; a2.w += pa.z * xa.w;
                a3.x += pa.w * xa.x; a3.y += pa.w * xa.y; a3.z += pa.w * xa.z; a3.w += pa.w * xa.w;
                dn.x += pa.x; dn.y += pa.y; dn.z += pa.z; dn.w += pa.w;
            }
        }
        float4 c0, c1, c2, c3;
        c0.x = __uint_as_float(f2tf32(a0.x)); c0.y = __uint_as_float(f2tf32(a0.y));
        c0.z = __uint_as_float(f2tf32(a0.z)); c0.w = __uint_as_float(f2tf32(a0.w));
        c1.x = __uint_as_float(f2tf32(a1.x)); c1.y = __uint_as_float(f2tf32(a1.y));
        c1.z = __uint_as_float(f2tf32(a1.z)); c1.w = __uint_as_float(f2tf32(a1.w));
        c2.x = __uint_as_float(f2tf32(a2.x)); c2.y = __uint_as_float(f2tf32(a2.y));
        c2.z = __uint_as_float(f2tf32(a2.z)); c2.w = __uint_as_float(f2tf32(a2.w));
        c3.x = __uint_as_float(f2tf32(a3.x)); c3.y = __uint_as_float(f2tf32(a3.y));
        c3.z = __uint_as_float(f2tf32(a3.z)); c3.w = __uint_as_float(f2tf32(a3.w));
        *(float4*)&As[(0 * 32 + nl) * 132 + lane * 4] = c0;
        *(float4*)&As[(1 * 32 + nl) * 132 + lane * 4] = c1;
        *(float4*)&As[(2 * 32 + nl) * 132 + lane * 4] = c2;
        *(float4*)&As[(3 * 32 + nl) * 132 + lane * 4] = c3;
        if (lane == 0) {
            dens[nl * 4 + 0] = dn.x; dens[nl * 4 + 1] = dn.y;
            dens[nl * 4 + 2] = dn.z; dens[nl * 4 + 3] = dn.w;
        }
    }

    // prefetch Bs chunk 0 (overlaps with straggling gather warps)
#pragma unroll
    for (int i = 0; i < 4; i++) {
        int id = tid + i * 512;
        int kr = id >> 6, cq = id & 63;
        float4 v = *(const float4*)&W1[(size_t)kr * 256 + cq * 4];
        Bs[kr * 260 + cq * 4 + 0] = __uint_as_float(f2tf32(v.x));
        Bs[kr * 260 + cq * 4 + 1] = __uint_as_float(f2tf32(v.y));
        Bs[kr * 260 + cq * 4 + 2] = __uint_as_float(f2tf32(v.z));
        Bs[kr * 260 + cq * 4 + 3] = __uint_as_float(f2tf32(v.w));
    }
    __syncthreads();

    int wn = wid & 3;
    int wm = wid >> 2;
    int rowHalf = wm & 1;
    int colHalf = wm >> 1;
    float acc[4][4];
#pragma unroll
    for (int nt = 0; nt < 4; nt++)
#pragma unroll
        for (int r = 0; r < 4; r++) acc[nt][r] = 0.f;

    for (int kc = 0; kc < 4; kc++) {
#pragma unroll
        for (int kk = 0; kk < 32; kk += 8) {
            int k0 = kc * 32 + kk;
            int ar = wn * 32 + rowHalf * 16 + (lane >> 2);
            unsigned a0 = __float_as_uint(As[ar * 132 + k0 + (lane & 3)]);
            unsigned a1 = __float_as_uint(As[(ar + 8) * 132 + k0 + (lane & 3)]);
            unsigned a2 = __float_as_uint(As[ar * 132 + k0 + 4 + (lane & 3)]);
            unsigned a3 = __float_as_uint(As[(ar + 8) * 132 + k0 + 4 + (lane & 3)]);
#pragma unroll
            for (int nt = 0; nt < 4; nt++) {
                int cb = wn * 64 + colHalf * 32 + nt * 8 + (lane >> 2);
                unsigned b0 = __float_as_uint(Bs[(kk + (lane & 3)) * 260 + cb]);
                unsigned b1v = __float_as_uint(Bs[(kk + 4 + (lane & 3)) * 260 + cb]);
                mma_tf32(acc[nt][0], acc[nt][1], acc[nt][2], acc[nt][3],
                         a0, a1, a2, a3, b0, b1v);
            }
        }
        if (kc < 3) {
            __syncthreads();
#pragma unroll
            for (int i = 0; i < 4; i++) {
                int id = tid + i * 512;
                int kr = id >> 6, cq = id & 63;
                float4 v = *(const float4*)&W1[(size_t)((kc + 1) * 32 + kr) * 256 + cq * 4];
                Bs[kr * 260 + cq * 4 + 0] = __uint_as_float(f2tf32(v.x));
                Bs[kr * 260 + cq * 4 + 1] = __uint_as_float(f2tf32(v.y));
                Bs[kr * 260 + cq * 4 + 2] = __uint_as_float(f2tf32(v.z));
                Bs[kr * 260 + cq * 4 + 3] = __uint_as_float(f2tf32(v.w));
            }
            __syncthreads();
        }
    }

#pragma unroll
    for (int nt = 0; nt < 4; nt++) {
        int col = wn * 64 + colHalf * 32 + nt * 8 + 2 * (lane & 3);
        float bb0 = b1[col], bb1 = b1[col + 1];
#pragma unroll
        for (int half = 0; half < 2; half++) {
            int r = rowHalf * 16 + (lane >> 2) + half * 8;
            int node = node0 + r;
            if (node < NN) {
                float inv = 1.0f / (dens[r * 4 + wn] + 1e-16f);
                float v0 = fmaxf(acc[nt][half * 2 + 0] * inv + bb0, 0.f);
                float v1 = fmaxf(acc[nt][half * 2 + 1] * inv + bb1, 0.f);
                *(float2*)&g_out1[(size_t)node * 256 + col] = make_float2(v0, v1);
            }
        }
    }
}

// ============ K4: g2 = out1 @ W2 (tf32, double-buffered) + fused alpha2 ============
#define G2_SMEM ((2 * 128 * 36 + 2 * 32 * 72 + 256) * 4)
__global__ void __launch_bounds__(256) gemm2_alpha2(const float* __restrict__ W2,
                                                    const float* __restrict__ a2s,
                                                    const float* __restrict__ a2d) {
    extern __shared__ float sm2[];
    float* AsB = sm2;
    float* BsB = sm2 + 2 * 4608;
    float* sred = sm2 + 2 * 4608 + 2 * 2304;
    int tid = threadIdx.x, lane = tid & 31, wid = tid >> 5;
    int wm = wid >> 1, wn = wid & 1;
    int br = blockIdx.x * 128;
    if (tid < 128) { sred[tid * 2] = 0.f; sred[tid * 2 + 1] = 0.f; }

    float acc[2][4][4];
#pragma unroll
    for (int mt = 0; mt < 2; mt++)
#pragma unroll
        for (int nt = 0; nt < 4; nt++)
#pragma unroll
            for (int r = 0; r < 4; r++) acc[mt][nt][r] = 0.f;

    auto load_chunk = [&](int buf, int k0) {
        float* As = AsB + buf * 4608;
        float* Bsc = BsB + buf * 2304;
#pragma unroll
        for (int i = 0; i < 4; i++) {
            int id = tid + i * 256;
            int row = id >> 3, kq = id & 7;
            int gr = br + row;
            float4 v = make_float4(0,0,0,0);
            if (gr < NN) v = *(const float4*)&g_out1[(size_t)gr * 256 + k0 + kq * 4];
            As[row * 36 + kq * 4 + 0] = __uint_as_float(f2tf32(v.x));
            As[row * 36 + kq * 4 + 1] = __uint_as_float(f2tf32(v.y));
            As[row * 36 + kq * 4 + 2] = __uint_as_float(f2tf32(v.z));
            As[row * 36 + kq * 4 + 3] = __uint_as_float(f2tf32(v.w));
        }
#pragma unroll
        for (int i = 0; i < 2; i++) {
            int id = tid + i * 256;
            int kr = id >> 4, cq = id & 15;
            float4 v = *(const float4*)&W2[(size_t)(k0 + kr) * 64 + cq * 4];
            Bsc[kr * 72 + cq * 4 + 0] = __uint_as_float(f2tf32(v.x));
            Bsc[kr * 72 + cq * 4 + 1] = __uint_as_float(f2tf32(v.y));
            Bsc[kr * 72 + cq * 4 + 2] = __uint_as_float(f2tf32(v.z));
            Bsc[kr * 72 + cq * 4 + 3] = __uint_as_float(f2tf32(v.w));
        }
    };

    load_chunk(0, 0);
    __syncthreads();

    for (int c = 0; c < 8; c++) {
        int buf = c & 1;
        if (c < 7) load_chunk(buf ^ 1, (c + 1) * 32);
        float* As = AsB + buf * 4608;
        float* Bsc = BsB + buf * 2304;
#pragma unroll
        for (int kk = 0; kk < 32; kk += 8) {
            unsigned af[2][4];
#pragma unroll
            for (int mt = 0; mt < 2; mt++) {
                int rb = wm * 32 + mt * 16 + (lane >> 2);
                af[mt][0] = __float_as_uint(As[rb * 36 + kk + (lane & 3)]);
                af[mt][1] = __float_as_uint(As[(rb + 8) * 36 + kk + (lane & 3)]);
                af[mt][2] = __float_as_uint(As[rb * 36 + kk + 4 + (lane & 3)]);
                af[mt][3] = __float_as_uint(As[(rb + 8) * 36 + kk + 4 + (lane & 3)]);
            }
            unsigned bf[4][2];
#pragma unroll
            for (int nt = 0; nt < 4; nt++) {
                int cb = wn * 32 + nt * 8 + (lane >> 2);
                bf[nt][0] = __float_as_uint(Bsc[(kk + (lane & 3)) * 72 + cb]);
                bf[nt][1] = __float_as_uint(Bsc[(kk + 4 + (lane & 3)) * 72 + cb]);
            }
#pragma unroll
            for (int mt = 0; mt < 2; mt++)
#pragma unroll
                for (int nt = 0; nt < 4; nt++)
                    mma_tf32(acc[mt][nt][0], acc[mt][nt][1], acc[mt][nt][2], acc[mt][nt][3],
                             af[mt][0], af[mt][1], af[mt][2], af[mt][3],
                             bf[nt][0], bf[nt][1]);
        }
        __syncthreads();
    }

#pragma unroll
    for (int mt = 0; mt < 2; mt++) {
#pragma unroll
        for (int half = 0; half < 2; half++) {
            int rl = wm * 32 + mt * 16 + (lane >> 2) + half * 8;
            int row = br + rl;
            float ss = 0.f, sd = 0.f;
            if (row < NN) {
#pragma unroll
                for (int nt = 0; nt < 4; nt++) {
                    int col = wn * 32 + nt * 8 + 2 * (lane & 3);
                    float v0 = acc[mt][nt][half * 2 + 0];
                    float v1 = acc[mt][nt][half * 2 + 1];
                    *(float2*)&g_g2[(size_t)row * 64 + col] = make_float2(v0, v1);
                    ss += v0 * a2s[col] + v1 * a2s[col + 1];
                    sd += v0 * a2d[col] + v1 * a2d[col + 1];
                }
                atomicAdd(&sred[rl * 2], ss);
                atomicAdd(&sred[rl * 2 + 1], sd);
            }
        }
    }
    __syncthreads();
    if (tid < 128) {
        int row = br + tid;
        if (row < NN) {
            g_asrc2[row] = sred[tid * 2];
            g_adst2[row] = sred[tid * 2 + 1];
        }
    }
}

// ============ K5: layer2 gather-aggregate (MLP-8) + norm/bias/relu + FC ============
__global__ void __launch_bounds__(256) aggr2_fc(const float* __restrict__ b2,
                                                const float* __restrict__ Wfc,
                                                const float* __restrict__ bfc,
                                                float* __restrict__ out) {
    __shared__ float wf[64 * ACT];
    for (int i = threadIdx.x; i < 64 * ACT; i += blockDim.x)
        wf[i] = Wfc[i];
    __syncthreads();
    int node = blockIdx.x * 8 + (threadIdx.x >> 5);
    int lane = threadIdx.x & 31;
    if (node >= NN) return;
    float ad = g_adst2[node];
    int s0 = g_off[node], s1 = g_off[node + 1];
    float2 acc = make_float2(0.f, 0.f);
    float den = 0.f;
    int i = s0;
    for (; i + 7 < s1; i += 8) {
        int e0 = g_csr[i],     e1 = g_csr[i + 1], e2 = g_csr[i + 2], e3 = g_csr[i + 3];
        int e4 = g_csr[i + 4], e5 = g_csr[i + 5], e6 = g_csr[i + 6], e7 = g_csr[i + 7];
        float l0 = g_asrc2[e0], l1 = g_asrc2[e1], l2 = g_asrc2[e2], l3 = g_asrc2[e3];
        float l4 = g_asrc2[e4], l5 = g_asrc2[e5], l6 = g_asrc2[e6], l7 = g_asrc2[e7];
        float2 v0 = *(const float2*)&g_g2[(size_t)e0 * 64 + lane * 2];
        float2 v1 = *(const float2*)&g_g2[(size_t)e1 * 64 + lane * 2];
        float2 v2 = *(const float2*)&g_g2[(size_t)e2 * 64 + lane * 2];
        float2 v3 = *(const float2*)&g_g2[(size_t)e3 * 64 + lane * 2];
        float2 v4 = *(const float2*)&g_g2[(size_t)e4 * 64 + lane * 2];
        float2 v5 = *(const float2*)&g_g2[(size_t)e5 * 64 + lane * 2];
        float2 v6 = *(const float2*)&g_g2[(size_t)e6 * 64 + lane * 2];
        float2 v7 = *(const float2*)&g_g2[(size_t)e7 * 64 + lane * 2];
        float p0 = __expf(lrelu(l0 + ad));
        float p1 = __expf(lrelu(l1 + ad));
        float p2 = __expf(lrelu(l2 + ad));
        float p3 = __expf(lrelu(l3 + ad));
        float p4 = __expf(lrelu(l4 + ad));
        float p5 = __expf(lrelu(l5 + ad));
        float p6 = __expf(lrelu(l6 + ad));
        float p7 = __expf(lrelu(l7 + ad));
        acc.x += p0 * v0.x + p1 * v1.x + p2 * v2.x + p3 * v3.x
               + p4 * v4.x + p5 * v5.x + p6 * v6.x + p7 * v7.x;
        acc.y += p0 * v0.y + p1 * v1.y + p2 * v2.y + p3 * v3.y
               + p4 * v4.y + p5 * v5.y + p6 * v6.y + p7 * v7.y;
        den += p0 + p1 + p2 + p3 + p4 + p5 + p6 + p7;
    }
    for (; i < s1; i++) {
        int sa = g_csr[i];
        float pa = __expf(lrelu(g_asrc2[sa] + ad));
        float2 va = *(const float2*)&g_g2[(size_t)sa * 64 + lane * 2];
        acc.x += pa * va.x;
        acc.y += pa * va.y;
        den += pa;
    }
    float inv = 1.0f / (den + 1e-16f);
    float2 bb = *(const float2*)&b2[lane * 2];
    float ox = fmaxf(acc.x * inv + bb.x, 0.f);
    float oy = fmaxf(acc.y * inv + bb.y, 0.f);
    float fa[ACT];
#pragma unroll
    for (int a = 0; a < ACT; a++)
        fa[a] = ox * wf[(2 * lane) * ACT + a] + oy * wf[(2 * lane + 1) * ACT + a];
#pragma unroll
    for (int a = 0; a < ACT; a++) {
#pragma unroll
        for (int o = 16; o > 0; o >>= 1)
            fa[a] += __shfl_down_sync(~0u, fa[a], o);
    }
    if (lane == 0) {
#pragma unroll
        for (int a = 0; a < ACT; a++)
            out[node * ACT + a] = fa[a] + bfc[a];
    }
}

// ---------------- launch ----------------
extern "C" void kernel_launch(void* const* d_in, const int* in_sizes, int n_in,
                              void* d_out, int out_size) {
    const float* x      = (const float*)d_in[0];
    const int*   ei     = (const int*)  d_in[1];
    const float* W1     = (const float*)d_in[2];
    const float* a1_src = (const float*)d_in[3];
    const float* a1_dst = (const float*)d_in[4];
    const float* b1     = (const float*)d_in[5];
    const float* W2     = (const float*)d_in[6];
    const float* a2_src = (const float*)d_in[7];
    const float* a2_dst = (const float*)d_in[8];
    const float* b2     = (const float*)d_in[9];
    const float* Wfc    = (const float*)d_in[10];
    const float* bfc    = (const float*)d_in[11];
    float* out = (float*)d_out;

    int E = in_sizes[1] / 2;
    int histB = (E + 511) / 512;

    cudaFuncSetAttribute(layer1_fused, cudaFuncAttributeMaxDynamicSharedMemorySize, L1_SMEM);
    cudaFuncSetAttribute(gemm2_alpha2, cudaFuncAttributeMaxDynamicSharedMemorySize, G2_SMEM);

    // 0: histogram + w1a precompute + x->fp16 convert
    hist_wpre<<<histB + 4 + CVT_B, 256>>>(ei, E, histB, W1, a1_src, a1_dst, x);
    // 1: scan + alpha1
    scan_alpha<<<1 + (NN + 31) / 32, 1024>>>(x);
    // 2: scatter + softmax weights (2 edges/thread)
    scatter_p<<<(E + NN + 511) / 512, 256>>>(ei, E);
    // 3: fused gather (fp16 x) + GEMM1 + epilogue   (<- profiled launch)
    layer1_fused<<<(NN + 31) / 32, 512, L1_SMEM>>>(x, W1, b1);
    // 4: GEMM2 double-buffered + alpha2
    gemm2_alpha2<<<(NN + 127) / 128, 256, G2_SMEM>>>(W2, a2_src, a2_dst);
    // 5: layer2 aggregate + FC (MLP-8)
    aggr2_fc<<<(NN + 7) / 8, 256>>>(b2, Wfc, bfc, out);
}

// round 17
// speedup vs baseline: 1.0105x; 1.0105x over previous
#include <cuda_runtime.h>
#include <cuda_bf16.h>
#include <cuda_fp16.h>
#include <math.h>

#define NN    50000
#define EE    800000
#define INCH  128
#define HID   64
#define HEADS 4
#define ACT   5

// ---------------- scratch ----------------
__device__ float g_out1[NN * 256];
__device__ float g_asrc1[NN * 4];
__device__ float g_adst1[NN * 4];
__device__ float g_g2[NN * 64];
__device__ float g_asrc2[NN];
__device__ float g_adst2[NN];
__device__ float g_w1a[128 * 8];
__device__ __half g_xh[NN * 128];
__device__ int   g_cnt[NN];
__device__ int   g_off[NN + 1];
__device__ int   g_pos[NN];
__device__ int   g_csr[EE + NN];
__device__ float g_p[(EE + NN) * 4];

__device__ __forceinline__ float lrelu(float x) { return x > 0.0f ? x : 0.2f * x; }

__device__ __forceinline__ unsigned f2tf32(float f) {
    unsigned u;
    asm("cvt.rna.tf32.f32 %0, %1;" : "=r"(u) : "f"(f));
    return u;
}

__device__ __forceinline__ void mma_tf32(float& d0, float& d1, float& d2, float& d3,
                                         unsigned a0, unsigned a1, unsigned a2, unsigned a3,
                                         unsigned b0, unsigned b1) {
    asm volatile("mma.sync.aligned.m16n8k8.row.col.f32.tf32.tf32.f32 "
                 "{%0,%1,%2,%3},{%4,%5,%6,%7},{%8,%9},{%0,%1,%2,%3};"
                 : "+f"(d0), "+f"(d1), "+f"(d2), "+f"(d3)
                 : "r"(a0), "r"(a1), "r"(a2), "r"(a3), "r"(b0), "r"(b1));
}

__device__ __forceinline__ float4 h2f4(uint2 h) {
    float2 lo = __half22float2(*(__half2*)&h.x);
    float2 hi = __half22float2(*(__half2*)&h.y);
    return make_float4(lo.x, lo.y, hi.x, hi.y);
}

// FMA of one edge: acc_h += p_h * xv  (16 fma + 4 add)
#define EDGE_FMA(P, XV)                                                     \
    do {                                                                    \
        a0.x += (P).x*(XV).x; a0.y += (P).x*(XV).y;                         \
        a0.z += (P).x*(XV).z; a0.w += (P).x*(XV).w;                         \
        a1.x += (P).y*(XV).x; a1.y += (P).y*(XV).y;                         \
        a1.z += (P).y*(XV).z; a1.w += (P).y*(XV).w;                         \
        a2.x += (P).z*(XV).x; a2.y += (P).z*(XV).y;                         \
        a2.z += (P).z*(XV).z; a2.w += (P).z*(XV).w;                         \
        a3.x += (P).w*(XV).x; a3.y += (P).w*(XV).y;                         \
        a3.z += (P).w*(XV).z; a3.w += (P).w*(XV).w;                         \
        dn.x += (P).x; dn.y += (P).y; dn.z += (P).z; dn.w += (P).w;         \
    } while (0)

#define CVT_B ((NN * 128 / 16 + 255) / 256)

// ============ K0: histogram (2 edges/thread) + w1a precompute + x->fp16 ============
__global__ void hist_wpre(const int* __restrict__ ei, int E, int histB,
                          const float* __restrict__ W1,
                          const float* __restrict__ a1s,
                          const float* __restrict__ a1d,
                          const float* __restrict__ x) {
    if ((int)blockIdx.x < histB) {
        int e0 = blockIdx.x * 512 + threadIdx.x;
        int e1 = e0 + 256;
        int d0 = (e0 < E) ? ei[E + e0] : -1;
        int d1 = (e1 < E) ? ei[E + e1] : -1;
        if (d0 >= 0) atomicAdd(&g_cnt[d0], 1);
        if (d1 >= 0) atomicAdd(&g_cnt[d1], 1);
    } else if ((int)blockIdx.x < histB + 4) {
        int t = (blockIdx.x - histB) * 256 + threadIdx.x;
        if (t < 1024) {
            int k = t >> 3, j = t & 7, h = j & 3;
            const float* av = (j < 4 ? a1s : a1d) + h * 64;
            const float* wr = W1 + (size_t)k * 256 + h * 64;
            float s = 0.f;
#pragma unroll 8
            for (int c = 0; c < 64; c++) s += wr[c] * av[c];
            g_w1a[k * 8 + j] = s;
        }
    } else {
        size_t base = ((size_t)(blockIdx.x - histB - 4) * 256 + threadIdx.x) * 16;
        if (base < (size_t)NN * 128) {
#pragma unroll
            for (int j = 0; j < 4; j++) {
                float4 v = *(const float4*)&x[base + j * 4];
                __half2 h0 = __floats2half2_rn(v.x, v.y);
                __half2 h1 = __floats2half2_rn(v.z, v.w);
                uint2 pk;
                pk.x = *(unsigned*)&h0;
                pk.y = *(unsigned*)&h1;
                *(uint2*)&g_xh[base + j * 4] = pk;
            }
        }
    }
}

// ============ K1: scan (block 0) + alpha1 (blocks 1..) ============
__global__ void __launch_bounds__(1024) scan_alpha(const float* __restrict__ x) {
    __shared__ float w1s[128 * 8];
    if (blockIdx.x == 0) {
        __shared__ int ws[32];
        const int T = 1024;
        const int CH = (NN + T - 1) / T;
        int tid = threadIdx.x;
        int base = tid * CH;
        int cnts[49];
        int local = 0;
        for (int j = 0; j < CH; j++) {
            int idx = base + j;
            int c = 0;
            if (idx < NN) { c = g_cnt[idx] + 1; g_cnt[idx] = 0; }
            cnts[j] = c;
            local += c;
        }
        int lane = tid & 31, wid = tid >> 5;
        int v = local;
#pragma unroll
        for (int o = 1; o < 32; o <<= 1) { int y = __shfl_up_sync(~0u, v, o); if (lane >= o) v += y; }
        if (lane == 31) ws[wid] = v;
        __syncthreads();
        if (wid == 0) {
            int w = ws[lane];
#pragma unroll
            for (int o = 1; o < 32; o <<= 1) { int y = __shfl_up_sync(~0u, w, o); if (lane >= o) w += y; }
            ws[lane] = w;
        }
        __syncthreads();
        int run = v - local + (wid > 0 ? ws[wid - 1] : 0);
        for (int j = 0; j < CH; j++) {
            int idx = base + j;
            if (idx < NN) {
                g_off[idx] = run;
                g_pos[idx] = run;
                run += cnts[j];
            }
        }
        if (tid == T - 1) g_off[NN] = run;
    } else {
        int tid = threadIdx.x;
        if (tid < 1024) w1s[tid] = g_w1a[tid];
        __syncthreads();
        int wid = tid >> 5, lane = tid & 31;
        int node = (blockIdx.x - 1) * 32 + wid;
        if (node >= NN) return;
        float4 xv = *(const float4*)&x[(size_t)node * 128 + lane * 4];
        float s[8];
#pragma unroll
        for (int j = 0; j < 8; j++) s[j] = 0.f;
#pragma unroll
        for (int k = 0; k < 4; k++) {
            float xk = (&xv.x)[k];
            const float* wr = &w1s[(lane * 4 + k) * 8];
            float4 wa = *(const float4*)&wr[0];
            float4 wb = *(const float4*)&wr[4];
            s[0] += xk * wa.x; s[1] += xk * wa.y; s[2] += xk * wa.z; s[3] += xk * wa.w;
            s[4] += xk * wb.x; s[5] += xk * wb.y; s[6] += xk * wb.z; s[7] += xk * wb.w;
        }
#pragma unroll
        for (int j = 0; j < 8; j++) {
#pragma unroll
            for (int o = 16; o > 0; o >>= 1) s[j] += __shfl_xor_sync(~0u, s[j], o);
        }
        if (lane == 0) {
            *(float4*)&g_asrc1[node * 4] = make_float4(s[0], s[1], s[2], s[3]);
            *(float4*)&g_adst1[node * 4] = make_float4(s[4], s[5], s[6], s[7]);
        }
    }
}

// ============ K2: scatter + softmax weights (2 edges/thread) ============
__global__ void scatter_p(const int* __restrict__ ei, int E) {
    int base = (blockIdx.x * blockDim.x + threadIdx.x) * 2;
#pragma unroll
    for (int j = 0; j < 2; j++) {
        int t = base + j;
        int src, dst;
        if (t < E) { src = ei[t]; dst = ei[E + t]; }
        else if (t < E + NN) { src = dst = t - E; }
        else continue;
        int pos = atomicAdd(&g_pos[dst], 1);
        g_csr[pos] = src;
        float4 es = *(const float4*)&g_asrc1[src * 4];
        float4 ed = *(const float4*)&g_adst1[dst * 4];
        float4 p;
        p.x = __expf(lrelu(es.x + ed.x));
        p.y = __expf(lrelu(es.y + ed.y));
        p.z = __expf(lrelu(es.z + ed.z));
        p.w = __expf(lrelu(es.w + ed.w));
        *(float4*)&g_p[(size_t)pos * 4] = p;
    }
}

// ============ K3: fused gather (fp16 x, MLP-8, dynamic queue) + tf32 GEMM1 ============
#define L1_SMEM ((128 * 132 + 32 * 260 + 128 + 32) * 4)
__global__ void __launch_bounds__(512, 2) layer1_fused(const float* __restrict__ x,
                                                       const float* __restrict__ W1,
                                                       const float* __restrict__ b1) {
    extern __shared__ float sm[];
    float* As = sm;                       // 128 rows (head*32+node) x 132
    float* Bs = sm + 128 * 132;           // 32 k x 260
    float* dens = Bs + 32 * 260;          // 128
    int*   q = (int*)(dens + 128);
    int tid = threadIdx.x, lane = tid & 31, wid = tid >> 5;
    int node0 = blockIdx.x * 32;

    if (tid == 0) q[0] = 0;
    __syncthreads();

    for (;;) {
        int nl;
        if (lane == 0) nl = atomicAdd(q, 1);
        nl = __shfl_sync(~0u, nl, 0);
        if (nl >= 32) break;
        int node = node0 + nl;
        float4 a0 = make_float4(0,0,0,0), a1 = a0, a2 = a0, a3 = a0;
        float4 dn = a0;
        if (node < NN) {
            int s0 = g_off[node], s1 = g_off[node + 1];
            int i = s0;
            // ---- unroll-8: 8 x-loads in flight ----
            for (; i + 7 < s1; i += 8) {
                int e0 = g_csr[i],     e1 = g_csr[i + 1];
                int e2 = g_csr[i + 2], e3 = g_csr[i + 3];
                int e4 = g_csr[i + 4], e5 = g_csr[i + 5];
                int e6 = g_csr[i + 6], e7 = g_csr[i + 7];
                uint2 h0 = *(const uint2*)&g_xh[(size_t)e0 * 128 + lane * 4];
                uint2 h1 = *(const uint2*)&g_xh[(size_t)e1 * 128 + lane * 4];
                uint2 h2 = *(const uint2*)&g_xh[(size_t)e2 * 128 + lane * 4];
                uint2 h3 = *(const uint2*)&g_xh[(size_t)e3 * 128 + lane * 4];
                uint2 h4 = *(const uint2*)&g_xh[(size_t)e4 * 128 + lane * 4];
                uint2 h5 = *(const uint2*)&g_xh[(size_t)e5 * 128 + lane * 4];
                uint2 h6 = *(const uint2*)&g_xh[(size_t)e6 * 128 + lane * 4];
                uint2 h7 = *(const uint2*)&g_xh[(size_t)e7 * 128 + lane * 4];
                {
                    float4 p0 = *(const float4*)&g_p[(size_t)(i)     * 4];
                    float4 p1 = *(const float4*)&g_p[(size_t)(i + 1) * 4];
                    float4 p2 = *(const float4*)&g_p[(size_t)(i + 2) * 4];
                    float4 p3 = *(const float4*)&g_p[(size_t)(i + 3) * 4];
                    float4 xv;
                    xv = h2f4(h0); EDGE_FMA(p0, xv);
                    xv = h2f4(h1); EDGE_FMA(p1, xv);
                    xv = h2f4(h2); EDGE_FMA(p2, xv);
                    xv = h2f4(h3); EDGE_FMA(p3, xv);
                }
                {
                    float4 p4 = *(const float4*)&g_p[(size_t)(i + 4) * 4];
                    float4 p5 = *(const float4*)&g_p[(size_t)(i + 5) * 4];
                    float4 p6 = *(const float4*)&g_p[(size_t)(i + 6) * 4];
                    float4 p7 = *(const float4*)&g_p[(size_t)(i + 7) * 4];
                    float4 xv;
                    xv = h2f4(h4); EDGE_FMA(p4, xv);
                    xv = h2f4(h5); EDGE_FMA(p5, xv);
                    xv = h2f4(h6); EDGE_FMA(p6, xv);
                    xv = h2f4(h7); EDGE_FMA(p7, xv);
                }
            }
            // ---- unroll-4 remainder ----
            for (; i + 3 < s1; i += 4) {
                int e0 = g_csr[i],     e1 = g_csr[i + 1];
                int e2 = g_csr[i + 2], e3 = g_csr[i + 3];
                uint2 h0 = *(const uint2*)&g_xh[(size_t)e0 * 128 + lane * 4];
                uint2 h1 = *(const uint2*)&g_xh[(size_t)e1 * 128 + lane * 4];
                uint2 h2 = *(const uint2*)&g_xh[(size_t)e2 * 128 + lane * 4];
                uint2 h3 = *(const uint2*)&g_xh[(size_t)e3 * 128 + lane * 4];
                float4 p0 = *(const float4*)&g_p[(size_t)(i)     * 4];
                float4 p1 = *(const float4*)&g_p[(size_t)(i + 1) * 4];
                float4 p2 = *(const float4*)&g_p[(size_t)(i + 2) * 4];
                float4 p3 = *(const float4*)&g_p[(size_t)(i + 3) * 4];
                float4 xv;
                xv = h2f4(h0); EDGE_FMA(p0, xv);
                xv = h2f4(h1); EDGE_FMA(p1, xv);
                xv = h2f4(h2); EDGE_FMA(p2, xv);
                xv = h2f4(h3); EDGE_FMA(p3, xv);
            }
            // ---- scalar tail ----
            for (; i < s1; i++) {
                int sa = g_csr[i];
                float4 pa = *(const float4*)&g_p[(size_t)i * 4];
                uint2 ha = *(const uint2*)&g_xh[(size_t)sa * 128 + lane * 4];
                float4 xv = h2f4(ha);
                EDGE_FMA(pa, xv);
            }
        }
        float4 c0, c1, c2, c3;
        c0.x = __uint_as_float(f2tf32(a0.x)); c0.y = __uint_as_float(f2tf32(a0.y));
        c0.z = __uint_as_float(f2tf32(a0.z)); c0.w = __uint_as_float(f2tf32(a0.w));
        c1.x = __uint_as_float(f2tf32(a1.x)); c1.y = __uint_as_float(f2tf32(a1.y));
        c1.z = __uint_as_float(f2tf32(a1.z)); c1.w = __uint_as_float(f2tf32(a1.w));
        c2.x = __uint_as_float(f2tf32(a2.x)); c2.y = __uint_as_float(f2tf32(a2.y));
        c2.z = __uint_as_float(f2tf32(a2.z)); c2.w = __uint_as_float(f2tf32(a2.w));
        c3.x = __uint_as_float(f2tf32(a3.x)); c3.y = __uint_as_float(f2tf32(a3.y));
        c3.z = __uint_as_float(f2tf32(a3.z)); c3.w = __uint_as_float(f2tf32(a3.w));
        *(float4*)&As[(0 * 32 + nl) * 132 + lane * 4] = c0;
        *(float4*)&As[(1 * 32 + nl) * 132 + lane * 4] = c1;
        *(float4*)&As[(2 * 32 + nl) * 132 + lane * 4] = c2;
        *(float4*)&As[(3 * 32 + nl) * 132 + lane * 4] = c3;
        if (lane == 0) {
            dens[nl * 4 + 0] = dn.x; dens[nl * 4 + 1] = dn.y;
            dens[nl * 4 + 2] = dn.z; dens[nl * 4 + 3] = dn.w;
        }
    }

    // prefetch Bs chunk 0 (overlaps with straggling gather warps)
#pragma unroll
    for (int i = 0; i < 4; i++) {
        int id = tid + i * 512;
        int kr = id >> 6, cq = id & 63;
        float4 v = *(const float4*)&W1[(size_t)kr * 256 + cq * 4];
        Bs[kr * 260 + cq * 4 + 0] = __uint_as_float(f2tf32(v.x));
        Bs[kr * 260 + cq * 4 + 1] = __uint_as_float(f2tf32(v.y));
        Bs[kr * 260 + cq * 4 + 2] = __uint_as_float(f2tf32(v.z));
        Bs[kr * 260 + cq * 4 + 3] = __uint_as_float(f2tf32(v.w));
    }
    __syncthreads();

    int wn = wid & 3;
    int wm = wid >> 2;
    int rowHalf = wm & 1;
    int colHalf = wm >> 1;
    float acc[4][4];
#pragma unroll
    for (int nt = 0; nt < 4; nt++)
#pragma unroll
        for (int r = 0; r < 4; r++) acc[nt][r] = 0.f;

    for (int kc = 0; kc < 4; kc++) {
#pragma unroll
        for (int kk = 0; kk < 32; kk += 8) {
            int k0 = kc * 32 + kk;
            int ar = wn * 32 + rowHalf * 16 + (lane >> 2);
            unsigned a0 = __float_as_uint(As[ar * 132 + k0 + (lane & 3)]);
            unsigned a1 = __float_as_uint(As[(ar + 8) * 132 + k0 + (lane & 3)]);
            unsigned a2 = __float_as_uint(As[ar * 132 + k0 + 4 + (lane & 3)]);
            unsigned a3 = __float_as_uint(As[(ar + 8) * 132 + k0 + 4 + (lane & 3)]);
#pragma unroll
            for (int nt = 0; nt < 4; nt++) {
                int cb = wn * 64 + colHalf * 32 + nt * 8 + (lane >> 2);
                unsigned b0 = __float_as_uint(Bs[(kk + (lane & 3)) * 260 + cb]);
                unsigned b1v = __float_as_uint(Bs[(kk + 4 + (lane & 3)) * 260 + cb]);
                mma_tf32(acc[nt][0], acc[nt][1], acc[nt][2], acc[nt][3],
                         a0, a1, a2, a3, b0, b1v);
            }
        }
        if (kc < 3) {
            __syncthreads();
#pragma unroll
            for (int i = 0; i < 4; i++) {
                int id = tid + i * 512;
                int kr = id >> 6, cq = id & 63;
                float4 v = *(const float4*)&W1[(size_t)((kc + 1) * 32 + kr) * 256 + cq * 4];
                Bs[kr * 260 + cq * 4 + 0] = __uint_as_float(f2tf32(v.x));
                Bs[kr * 260 + cq * 4 + 1] = __uint_as_float(f2tf32(v.y));
                Bs[kr * 260 + cq * 4 + 2] = __uint_as_float(f2tf32(v.z));
                Bs[kr * 260 + cq * 4 + 3] = __uint_as_float(f2tf32(v.w));
            }
            __syncthreads();
        }
    }

#pragma unroll
    for (int nt = 0; nt < 4; nt++) {
        int col = wn * 64 + colHalf * 32 + nt * 8 + 2 * (lane & 3);
        float bb0 = b1[col], bb1 = b1[col + 1];
#pragma unroll
        for (int half = 0; half < 2; half++) {
            int r = rowHalf * 16 + (lane >> 2) + half * 8;
            int node = node0 + r;
            if (node < NN) {
                float inv = 1.0f / (dens[r * 4 + wn] + 1e-16f);
                float v0 = fmaxf(acc[nt][half * 2 + 0] * inv + bb0, 0.f);
                float v1 = fmaxf(acc[nt][half * 2 + 1] * inv + bb1, 0.f);
                *(float2*)&g_out1[(size_t)node * 256 + col] = make_float2(v0, v1);
            }
        }
    }
}

// ============ K4: g2 = out1 @ W2 (tf32, double-buffered) + fused alpha2 ============
#define G2_SMEM ((2 * 128 * 36 + 2 * 32 * 72 + 256) * 4)
__global__ void __launch_bounds__(256) gemm2_alpha2(const float* __restrict__ W2,
                                                    const float* __restrict__ a2s,
                                                    const float* __restrict__ a2d) {
    extern __shared__ float sm2[];
    float* AsB = sm2;
    float* BsB = sm2 + 2 * 4608;
    float* sred = sm2 + 2 * 4608 + 2 * 2304;
    int tid = threadIdx.x, lane = tid & 31, wid = tid >> 5;
    int wm = wid >> 1, wn = wid & 1;
    int br = blockIdx.x * 128;
    if (tid < 128) { sred[tid * 2] = 0.f; sred[tid * 2 + 1] = 0.f; }

    float acc[2][4][4];
#pragma unroll
    for (int mt = 0; mt < 2; mt++)
#pragma unroll
        for (int nt = 0; nt < 4; nt++)
#pragma unroll
            for (int r = 0; r < 4; r++) acc[mt][nt][r] = 0.f;

    auto load_chunk = [&](int buf, int k0) {
        float* As = AsB + buf * 4608;
        float* Bsc = BsB + buf * 2304;
#pragma unroll
        for (int i = 0; i < 4; i++) {
            int id = tid + i * 256;
            int row = id >> 3, kq = id & 7;
            int gr = br + row;
            float4 v = make_float4(0,0,0,0);
            if (gr < NN) v = *(const float4*)&g_out1[(size_t)gr * 256 + k0 + kq * 4];
            As[row * 36 + kq * 4 + 0] = __uint_as_float(f2tf32(v.x));
            As[row * 36 + kq * 4 + 1] = __uint_as_float(f2tf32(v.y));
            As[row * 36 + kq * 4 + 2] = __uint_as_float(f2tf32(v.z));
            As[row * 36 + kq * 4 + 3] = __uint_as_float(f2tf32(v.w));
        }
#pragma unroll
        for (int i = 0; i < 2; i++) {
            int id = tid + i * 256;
            int kr = id >> 4, cq = id & 15;
            float4 v = *(const float4*)&W2[(size_t)(k0 + kr) * 64 + cq * 4];
            Bsc[kr * 72 + cq * 4 + 0] = __uint_as_float(f2tf32(v.x));
            Bsc[kr * 72 + cq * 4 + 1] = __uint_as_float(f2tf32(v.y));
            Bsc[kr * 72 + cq * 4 + 2] = __uint_as_float(f2tf32(v.z));
            Bsc[kr * 72 + cq * 4 + 3] = __uint_as_float(f2tf32(v.w));
        }
    };

    load_chunk(0, 0);
    __syncthreads();

    for (int c = 0; c < 8; c++) {
        int buf = c & 1;
        if (c < 7) load_chunk(buf ^ 1, (c + 1) * 32);
        float* As = AsB + buf * 4608;
        float* Bsc = BsB + buf * 2304;
#pragma unroll
        for (int kk = 0; kk < 32; kk += 8) {
            unsigned af[2][4];
#pragma unroll
            for (int mt = 0; mt < 2; mt++) {
                int rb = wm * 32 + mt * 16 + (lane >> 2);
                af[mt][0] = __float_as_uint(As[rb * 36 + kk + (lane & 3)]);
                af[mt][1] = __float_as_uint(As[(rb + 8) * 36 + kk + (lane & 3)]);
                af[mt][2] = __float_as_uint(As[rb * 36 + kk + 4 + (lane & 3)]);
                af[mt][3] = __float_as_uint(As[(rb + 8) * 36 + kk + 4 + (lane & 3)]);
            }
            unsigned bf[4][2];
#pragma unroll
            for (int nt = 0; nt < 4; nt++) {
                int cb = wn * 32 + nt * 8 + (lane >> 2);
                bf[nt][0] = __float_as_uint(Bsc[(kk + (lane & 3)) * 72 + cb]);
                bf[nt][1] = __float_as_uint(Bsc[(kk + 4 + (lane & 3)) * 72 + cb]);
            }
#pragma unroll
            for (int mt = 0; mt < 2; mt++)
#pragma unroll
                for (int nt = 0; nt < 4; nt++)
                    mma_tf32(acc[mt][nt][0], acc[mt][nt][1], acc[mt][nt][2], acc[mt][nt][3],
                             af[mt][0], af[mt][1], af[mt][2], af[mt][3],
                             bf[nt][0], bf[nt][1]);
        }
        __syncthreads();
    }

#pragma unroll
    for (int mt = 0; mt < 2; mt++) {
#pragma unroll
        for (int half = 0; half < 2; half++) {
            int rl = wm * 32 + mt * 16 + (lane >> 2) + half * 8;
            int row = br + rl;
            float ss = 0.f, sd = 0.f;
            if (row < NN) {
#pragma unroll
                for (int nt = 0; nt < 4; nt++) {
                    int col = wn * 32 + nt * 8 + 2 * (lane & 3);
                    float v0 = acc[mt][nt][half * 2 + 0];
                    float v1 = acc[mt][nt][half * 2 + 1];
                    *(float2*)&g_g2[(size_t)row * 64 + col] = make_float2(v0, v1);
                    ss += v0 * a2s[col] + v1 * a2s[col + 1];
                    sd += v0 * a2d[col] + v1 * a2d[col + 1];
                }
                atomicAdd(&sred[rl * 2], ss);
                atomicAdd(&sred[rl * 2 + 1], sd);
            }
        }
    }
    __syncthreads();
    if (tid < 128) {
        int row = br + tid;
        if (row < NN) {
            g_asrc2[row] = sred[tid * 2];
            g_adst2[row] = sred[tid * 2 + 1];
        }
    }
}

// ============ K5: layer2 gather-aggregate (MLP-8) + norm/bias/relu + FC ============
__global__ void __launch_bounds__(256) aggr2_fc(const float* __restrict__ b2,
                                                const float* __restrict__ Wfc,
                                                const float* __restrict__ bfc,
                                                float* __restrict__ out) {
    __shared__ float wf[64 * ACT];
    for (int i = threadIdx.x; i < 64 * ACT; i += blockDim.x)
        wf[i] = Wfc[i];
    __syncthreads();
    int node = blockIdx.x * 8 + (threadIdx.x >> 5);
    int lane = threadIdx.x & 31;
    if (node >= NN) return;
    float ad = g_adst2[node];
    int s0 = g_off[node], s1 = g_off[node + 1];
    float2 acc = make_float2(0.f, 0.f);
    float den = 0.f;
    int i = s0;
    for (; i + 7 < s1; i += 8) {
        int e0 = g_csr[i],     e1 = g_csr[i + 1], e2 = g_csr[i + 2], e3 = g_csr[i + 3];
        int e4 = g_csr[i + 4], e5 = g_csr[i + 5], e6 = g_csr[i + 6], e7 = g_csr[i + 7];
        float l0 = g_asrc2[e0], l1 = g_asrc2[e1], l2 = g_asrc2[e2], l3 = g_asrc2[e3];
        float l4 = g_asrc2[e4], l5 = g_asrc2[e5], l6 = g_asrc2[e6], l7 = g_asrc2[e7];
        float2 v0 = *(const float2*)&g_g2[(size_t)e0 * 64 + lane * 2];
        float2 v1 = *(const float2*)&g_g2[(size_t)e1 * 64 + lane * 2];
        float2 v2 = *(const float2*)&g_g2[(size_t)e2 * 64 + lane * 2];
        float2 v3 = *(const float2*)&g_g2[(size_t)e3 * 64 + lane * 2];
        float2 v4 = *(const float2*)&g_g2[(size_t)e4 * 64 + lane * 2];
        float2 v5 = *(const float2*)&g_g2[(size_t)e5 * 64 + lane * 2];
        float2 v6 = *(const float2*)&g_g2[(size_t)e6 * 64 + lane * 2];
        float2 v7 = *(const float2*)&g_g2[(size_t)e7 * 64 + lane * 2];
        float p0 = __expf(lrelu(l0 + ad));
        float p1 = __expf(lrelu(l1 + ad));
        float p2 = __expf(lrelu(l2 + ad));
        float p3 = __expf(lrelu(l3 + ad));
        float p4 = __expf(lrelu(l4 + ad));
        float p5 = __expf(lrelu(l5 + ad));
        float p6 = __expf(lrelu(l6 + ad));
        float p7 = __expf(lrelu(l7 + ad));
        acc.x += p0 * v0.x + p1 * v1.x + p2 * v2.x + p3 * v3.x
               + p4 * v4.x + p5 * v5.x + p6 * v6.x + p7 * v7.x;
        acc.y += p0 * v0.y + p1 * v1.y + p2 * v2.y + p3 * v3.y
               + p4 * v4.y + p5 * v5.y + p6 * v6.y + p7 * v7.y;
        den += p0 + p1 + p2 + p3 + p4 + p5 + p6 + p7;
    }
    for (; i < s1; i++) {
        int sa = g_csr[i];
        float pa = __expf(lrelu(g_asrc2[sa] + ad));
        float2 va = *(const float2*)&g_g2[(size_t)sa * 64 + lane * 2];
        acc.x += pa * va.x;
        acc.y += pa * va.y;
        den += pa;
    }
    float inv = 1.0f / (den + 1e-16f);
    float2 bb = *(const float2*)&b2[lane * 2];
    float ox = fmaxf(acc.x * inv + bb.x, 0.f);
    float oy = fmaxf(acc.y * inv + bb.y, 0.f);
    float fa[ACT];
#pragma unroll
    for (int a = 0; a < ACT; a++)
        fa[a] = ox * wf[(2 * lane) * ACT + a] + oy * wf[(2 * lane + 1) * ACT + a];
#pragma unroll
    for (int a = 0; a < ACT; a++) {
#pragma unroll
        for (int o = 16; o > 0; o >>= 1)
            fa[a] += __shfl_down_sync(~0u, fa[a], o);
    }
    if (lane == 0) {
#pragma unroll
        for (int a = 0; a < ACT; a++)
            out[node * ACT + a] = fa[a] + bfc[a];
    }
}

// ---------------- launch ----------------
extern "C" void kernel_launch(void* const* d_in, const int* in_sizes, int n_in,
                              void* d_out, int out_size) {
    const float* x      = (const float*)d_in[0];
    const int*   ei     = (const int*)  d_in[1];
    const float* W1     = (const float*)d_in[2];
    const float* a1_src = (const float*)d_in[3];
    const float* a1_dst = (const float*)d_in[4];
    const float* b1     = (const float*)d_in[5];
    const float* W2     = (const float*)d_in[6];
    const float* a2_src = (const float*)d_in[7];
    const float* a2_dst = (const float*)d_in[8];
    const float* b2     = (const float*)d_in[9];
    const float* Wfc    = (const float*)d_in[10];
    const float* bfc    = (const float*)d_in[11];
    float* out = (float*)d_out;

    int E = in_sizes[1] / 2;
    int histB = (E + 511) / 512;

    cudaFuncSetAttribute(layer1_fused, cudaFuncAttributeMaxDynamicSharedMemorySize, L1_SMEM);
    cudaFuncSetAttribute(gemm2_alpha2, cudaFuncAttributeMaxDynamicSharedMemorySize, G2_SMEM);

    // 0: histogram + w1a precompute + x->fp16 convert
    hist_wpre<<<histB + 4 + CVT_B, 256>>>(ei, E, histB, W1, a1_src, a1_dst, x);
    // 1: scan + alpha1
    scan_alpha<<<1 + (NN + 31) / 32, 1024>>>(x);
    // 2: scatter + softmax weights
    scatter_p<<<(E + NN + 511) / 512, 256>>>(ei, E);
    // 3: fused gather (fp16, MLP-8) + GEMM1 + epilogue   (<- profiled launch)
    layer1_fused<<<(NN + 31) / 32, 512, L1_SMEM>>>(x, W1, b1);
    // 4: GEMM2 double-buffered + alpha2
    gemm2_alpha2<<<(NN + 127) / 128, 256, G2_SMEM>>>(W2, a2_src, a2_dst);
    // 5: layer2 aggregate + FC (MLP-8)
    aggr2_fc<<<(NN + 7) / 8, 256>>>(b2, Wfc, bfc, out);
}